// round 5
// baseline (speedup 1.0000x reference)
#include <cuda_runtime.h>
#include <cstdint>

// Output: [N+2E, 2E+N] = [5120, 5120] float32, row-major (20480 B per row).
//   rows [0, N):        [ M (N x E) | 0 | 0 ]
//   rows [N, N+E):      [ 0 | I_E | -M^T (E x N) ]
//   rows [N+E, N+2E):   [ diag(z) | diag(y) | 0 ]
//
// Kernel 1 — block roles:
//   [0, 128):        TMA zero-fill: TOP rows, cols [2048,5120) (12288 B), 8 rows/blk
//   [128, 384):      TMA zero-fill: MID rows, cols [0,4096) (16384 B), 8 rows/blk
//   [384, 640):      TMA zero-fill: BOT rows, full row (20480 B), 8 rows/blk
//   [640, 1664):     M copy: one TOP row each (512 float4, 2/thread)
//   [1664, 3712):    -M^T 32x32 smem transpose
// Kernel 2 — patch identity / diag(z) / diag(y) (6144 scalar stores).

#define NN   1024
#define EE   2048
#define SIGW 64
#define CC   (2 * EE + NN)   // 5120
#define C4   (CC / 4)        // 1280
#define DTC  1e-6f

#define ZTOP_B 128
#define ZMID_B 256
#define ZBOT_B 256
#define MCP_B  1024
#define TR_B   2048
#define K1_B   (ZTOP_B + ZMID_B + ZBOT_B + MCP_B + TR_B)   // 3712

__device__ __forceinline__ uint32_t smem_u32(const void* p) {
    uint32_t a;
    asm("{ .reg .u64 t; cvta.to.shared.u64 t, %1; cvt.u32.u64 %0, t; }"
        : "=r"(a) : "l"(p));
    return a;
}

__device__ __forceinline__ void bulk_store(void* gptr, uint32_t saddr, uint32_t bytes) {
    asm volatile("cp.async.bulk.global.shared::cta.bulk_group [%0], [%1], %2;"
                 :: "l"(gptr), "r"(saddr), "r"(bytes) : "memory");
}

__global__ void __launch_bounds__(256)
coeff_fill_kernel(const float* __restrict__ M, float* __restrict__ out)
{
    __shared__ __align__(16) float4 zbuf[1280];   // 20 KB of zeros
    __shared__ float tile[32][33];

    const int b   = blockIdx.x;
    const int tid = threadIdx.x;

    if (b < ZTOP_B + ZMID_B + ZBOT_B) {
        // ---- TMA zero-fill ----
        const float4 zero4 = make_float4(0.f, 0.f, 0.f, 0.f);
        #pragma unroll
        for (int k = 0; k < 5; k++) zbuf[tid + k * 256] = zero4;
        __syncthreads();
        asm volatile("fence.proxy.async;" ::: "memory");

        if (tid == 0) {
            const uint32_t s = smem_u32(zbuf);
            if (b < ZTOP_B) {
                const int r0 = b * 8;               // TOP rows, cols [2048,5120)
                #pragma unroll
                for (int i = 0; i < 8; i++)
                    bulk_store(out + (size_t)(r0 + i) * CC + EE, s, 12288u);
            } else if (b < ZTOP_B + ZMID_B) {
                const int r0 = (b - ZTOP_B) * 8;    // MID rows, cols [0,4096)
                #pragma unroll
                for (int i = 0; i < 8; i++)
                    bulk_store(out + (size_t)(NN + r0 + i) * CC, s, 16384u);
            } else {
                const int r0 = (b - ZTOP_B - ZMID_B) * 8;  // BOT rows, full
                #pragma unroll
                for (int i = 0; i < 8; i++)
                    bulk_store(out + (size_t)(NN + EE + r0 + i) * CC, s, 20480u);
            }
            asm volatile("cp.async.bulk.commit_group;" ::: "memory");
            asm volatile("cp.async.bulk.wait_group 0;" ::: "memory");
        }
        return;
    }

    if (b < ZTOP_B + ZMID_B + ZBOT_B + MCP_B) {
        // ---- M copy: TOP row, cols [0, 2048). 512 float4, 2 per thread.
        const int row = b - (ZTOP_B + ZMID_B + ZBOT_B);
        const float4* Mrow = reinterpret_cast<const float4*>(M + (size_t)row * EE);
        float4* orow = reinterpret_cast<float4*>(out) + (size_t)row * C4;
        orow[tid]       = Mrow[tid];
        orow[tid + 256] = Mrow[tid + 256];
        return;
    }

    // ---- -M^T via smem transpose: out[N+e][2E+n] = -M[n][e].
    {
        const int t  = b - (ZTOP_B + ZMID_B + ZBOT_B + MCP_B);
        const int tn = t & 31;              // 32 tiles along n
        const int te = t >> 5;              // 64 tiles along e
        const int n0 = tn * 32;
        const int e0 = te * 32;
        const int tx = tid & 31;
        const int ty = tid >> 5;            // 0..7

        #pragma unroll
        for (int i = 0; i < 4; i++) {
            const int r = ty + i * 8;       // local n
            tile[r][tx] = M[(size_t)(n0 + r) * EE + (e0 + tx)];
        }
        __syncthreads();

        const int r = tid >> 3;             // local e, 0..31
        const int q = tid & 7;              // float4 slot along n
        float4 v;
        v.x = -tile[q * 4 + 0][r];
        v.y = -tile[q * 4 + 1][r];
        v.z = -tile[q * 4 + 2][r];
        v.w = -tile[q * 4 + 3][r];
        *reinterpret_cast<float4*>(
            out + (size_t)(NN + e0 + r) * CC + (2 * EE + n0 + q * 4)) = v;
    }
}

__global__ void __launch_bounds__(256)
coeff_patch_kernel(const float* __restrict__ params,
                   const float* __restrict__ sw_params,
                   const int*   __restrict__ kinds,
                   const int*   __restrict__ time_ptr,
                   float*       __restrict__ out)
{
    const int e = blockIdx.x * 256 + threadIdx.x;
    if (e >= EE) return;

    const int   tm    = *time_ptr;
    const float p     = params[e];
    const int   kk    = kinds[e];
    const bool  sw_on = sw_params[(size_t)e * SIGW + tm] > 0.0f;  // sigmoid(x)>0.5 <=> x>0
    const float ndt   = -DTC / p;

    float z, y;
    switch (kk) {
        case 0:  z = -p;                  y = 1.0f;                 break; // R
        case 1:  z = 0.0f;                y = 1.0f;                 break; // IVS
        case 2:  z = 1.0f;                y = 0.0f;                 break; // VC
        case 3:  z = sw_on ? 0.0f : 1.0f; y = sw_on ? 1.0f : 0.0f;  break; // SW
        case 4:  z = ndt;                 y = 1.0f;                 break; // C
        default: z = 1.0f;                y = ndt;                  break; // L
    }

    out[(size_t)(NN + e) * CC + EE + e]      = 1.0f;  // identity
    out[(size_t)(NN + EE + e) * CC + e]      = z;     // diag(z)
    out[(size_t)(NN + EE + e) * CC + EE + e] = y;     // diag(y)
}

extern "C" void kernel_launch(void* const* d_in, const int* in_sizes, int n_in,
                              void* d_out, int out_size)
{
    const float* M         = (const float*)d_in[0];
    const float* params    = (const float*)d_in[1];
    const float* sw_params = (const float*)d_in[2];
    const int*   kinds     = (const int*)d_in[3];
    const int*   time_ptr  = (const int*)d_in[4];
    float*       out       = (float*)d_out;

    coeff_fill_kernel<<<K1_B, 256>>>(M, out);
    coeff_patch_kernel<<<EE / 256, 256>>>(params, sw_params, kinds, time_ptr, out);
}

// round 6
// speedup vs baseline: 1.0783x; 1.0783x over previous
#include <cuda_runtime.h>
#include <cstdint>

// Output: [N+2E, 2E+N] = [5120, 5120] float32, row-major (20480 B per row).
//   rows [0, N):        [ M (N x E) | 0 | 0 ]
//   rows [N, N+E):      [ 0 | I_E | -M^T (E x N) ]
//   rows [N+E, N+2E):   [ diag(z) | diag(y) | 0 ]
//
// ONE kernel. Block roles:
//   [0, 128):        TMA zero: TOP rows, cols [2048,5120), 8 rows/blk
//   [128, 384):      TMA zero: MID rows, cols [0,4096), 8 rows/blk + identity patch
//   [384, 640):      TMA zero: BOT full rows, 8 rows/blk + z/y diagonal patch
//   [640, 1664):     M copy: one TOP row each (512 float4)
//   [1664, 3712):    -M^T 32x32 smem transpose

#define NN   1024
#define EE   2048
#define SIGW 64
#define CC   (2 * EE + NN)   // 5120
#define C4   (CC / 4)        // 1280
#define DTC  1e-6f

#define ZTOP_B 128
#define ZMID_B 256
#define ZBOT_B 256
#define MCP_B  1024
#define TR_B   2048
#define K1_B   (ZTOP_B + ZMID_B + ZBOT_B + MCP_B + TR_B)   // 3712

__device__ __forceinline__ uint32_t smem_u32(const void* p) {
    uint32_t a;
    asm("{ .reg .u64 t; cvta.to.shared.u64 t, %1; cvt.u32.u64 %0, t; }"
        : "=r"(a) : "l"(p));
    return a;
}

__device__ __forceinline__ void bulk_store(void* gptr, uint32_t saddr, uint32_t bytes) {
    asm volatile("cp.async.bulk.global.shared::cta.bulk_group [%0], [%1], %2;"
                 :: "l"(gptr), "r"(saddr), "r"(bytes) : "memory");
}

__global__ void __launch_bounds__(256)
coeff_build_kernel(const float* __restrict__ M,
                   const float* __restrict__ params,
                   const float* __restrict__ sw_params,
                   const int*   __restrict__ kinds,
                   const int*   __restrict__ time_ptr,
                   float*       __restrict__ out)
{
    // 20 KB shared buffer: zeros for TMA blocks; first 4.3 KB reused as the
    // transpose tile by transpose blocks (disjoint block roles).
    __shared__ __align__(16) float sbuf[5120];
    float (*tile)[33] = reinterpret_cast<float (*)[33]>(sbuf);

    const int b   = blockIdx.x;
    const int tid = threadIdx.x;

    if (b < ZTOP_B + ZMID_B + ZBOT_B) {
        // ================= TMA zero-fill (+ in-block diagonal patches) =====
        float4* z4 = reinterpret_cast<float4*>(sbuf);
        const float4 zero4 = make_float4(0.f, 0.f, 0.f, 0.f);
        #pragma unroll
        for (int k = 0; k < 5; k++) z4[tid + k * 256] = zero4;
        __syncthreads();
        asm volatile("fence.proxy.async;" ::: "memory");

        if (b < ZTOP_B) {
            // TOP rows r0..r0+7, cols [2048, 5120): pure zeros.
            if (tid == 0) {
                const uint32_t s = smem_u32(sbuf);
                const int r0 = b * 8;
                #pragma unroll
                for (int i = 0; i < 8; i++)
                    bulk_store(out + (size_t)(r0 + i) * CC + EE, s, 12288u);
                asm volatile("cp.async.bulk.commit_group;" ::: "memory");
                asm volatile("cp.async.bulk.wait_group 0;" ::: "memory");
            }
            return;
        }

        if (b < ZTOP_B + ZMID_B) {
            // MID rows: zeros cols [0,4096), then identity at (N+e, E+e).
            const int r0 = (b - ZTOP_B) * 8;     // e base
            if (tid == 0) {
                const uint32_t s = smem_u32(sbuf);
                #pragma unroll
                for (int i = 0; i < 8; i++)
                    bulk_store(out + (size_t)(NN + r0 + i) * CC, s, 16384u);
                asm volatile("cp.async.bulk.commit_group;" ::: "memory");
                asm volatile("cp.async.bulk.wait_group 0;" ::: "memory");
            }
            __syncthreads();                     // order patches after TMA done
            if (tid < 8) {
                const int e = r0 + tid;
                out[(size_t)(NN + e) * CC + EE + e] = 1.0f;
            }
            return;
        }

        {
            // BOT rows: full-row zeros, then diag(z) at col e, diag(y) at E+e.
            const int r0 = (b - ZTOP_B - ZMID_B) * 8;   // e base
            if (tid == 0) {
                const uint32_t s = smem_u32(sbuf);
                #pragma unroll
                for (int i = 0; i < 8; i++)
                    bulk_store(out + (size_t)(NN + EE + r0 + i) * CC, s, 20480u);
                asm volatile("cp.async.bulk.commit_group;" ::: "memory");
                asm volatile("cp.async.bulk.wait_group 0;" ::: "memory");
            }
            __syncthreads();
            if (tid < 8) {
                const int e = r0 + tid;
                const int   tm    = *time_ptr;
                const float p     = params[e];
                const int   kk    = kinds[e];
                const bool  sw_on = sw_params[(size_t)e * SIGW + tm] > 0.0f; // sigmoid>0.5 <=> x>0
                const float ndt   = -DTC / p;
                float z, y;
                switch (kk) {
                    case 0:  z = -p;                  y = 1.0f;                 break; // R
                    case 1:  z = 0.0f;                y = 1.0f;                 break; // IVS
                    case 2:  z = 1.0f;                y = 0.0f;                 break; // VC
                    case 3:  z = sw_on ? 0.0f : 1.0f; y = sw_on ? 1.0f : 0.0f;  break; // SW
                    case 4:  z = ndt;                 y = 1.0f;                 break; // C
                    default: z = 1.0f;                y = ndt;                  break; // L
                }
                out[(size_t)(NN + EE + e) * CC + e]      = z;
                out[(size_t)(NN + EE + e) * CC + EE + e] = y;
            }
            return;
        }
    }

    if (b < ZTOP_B + ZMID_B + ZBOT_B + MCP_B) {
        // ================= M copy: TOP row, cols [0, 2048) =================
        const int row = b - (ZTOP_B + ZMID_B + ZBOT_B);
        const float4* Mrow = reinterpret_cast<const float4*>(M + (size_t)row * EE);
        float4* orow = reinterpret_cast<float4*>(out) + (size_t)row * C4;
        orow[tid]       = Mrow[tid];
        orow[tid + 256] = Mrow[tid + 256];
        return;
    }

    // ================= -M^T via smem transpose =========================
    {
        const int t  = b - (ZTOP_B + ZMID_B + ZBOT_B + MCP_B);
        const int tn = t & 31;              // 32 tiles along n
        const int te = t >> 5;              // 64 tiles along e
        const int n0 = tn * 32;
        const int e0 = te * 32;
        const int tx = tid & 31;
        const int ty = tid >> 5;            // 0..7

        #pragma unroll
        for (int i = 0; i < 4; i++) {
            const int r = ty + i * 8;       // local n
            tile[r][tx] = M[(size_t)(n0 + r) * EE + (e0 + tx)];
        }
        __syncthreads();

        const int r = tid >> 3;             // local e, 0..31
        const int q = tid & 7;              // float4 slot along n
        float4 v;
        v.x = -tile[q * 4 + 0][r];
        v.y = -tile[q * 4 + 1][r];
        v.z = -tile[q * 4 + 2][r];
        v.w = -tile[q * 4 + 3][r];
        *reinterpret_cast<float4*>(
            out + (size_t)(NN + e0 + r) * CC + (2 * EE + n0 + q * 4)) = v;
    }
}

extern "C" void kernel_launch(void* const* d_in, const int* in_sizes, int n_in,
                              void* d_out, int out_size)
{
    const float* M         = (const float*)d_in[0];
    const float* params    = (const float*)d_in[1];
    const float* sw_params = (const float*)d_in[2];
    const int*   kinds     = (const int*)d_in[3];
    const int*   time_ptr  = (const int*)d_in[4];

    coeff_build_kernel<<<K1_B, 256>>>(M, params, sw_params, kinds, time_ptr,
                                      (float*)d_out);
}

// round 7
// speedup vs baseline: 1.0798x; 1.0014x over previous
#include <cuda_runtime.h>
#include <cstdint>

// Output: [N+2E, 2E+N] = [5120, 5120] float32, row-major (20480 B per row).
//   rows [0, N):        [ M (N x E) | 0 | 0 ]
//   rows [N, N+E):      [ 0 | I_E | -M^T (E x N) ]
//   rows [N+E, N+2E):   [ diag(z) | diag(y) | 0 ]
//
// ONE kernel, TMA-bulk-store based. Block roles:
//   [0, 128):        TOPZ: zeros for TOP rows cols [2048,5120), 8 rows/blk (TMA)
//   [128, 1152):     TOPM: M copy into TOP row cols [0,2048) (direct STG)
//   [1152, 3200):    MID : full smem image of row N+e cols [0,4096) incl. the
//                          identity 1.0, one 16 KB TMA bulk store
//   [3200, 5248):    BOT : full smem image of row N+E+e (z, y baked in),
//                          one 20 KB TMA bulk store
//   [5248, 7296):    TR  : -M^T 32x32 smem transpose (direct STG)

#define NN   1024
#define EE   2048
#define SIGW 64
#define CC   (2 * EE + NN)   // 5120
#define C4   (CC / 4)        // 1280
#define DTC  1e-6f

#define TOPZ_B 128
#define TOPM_B 1024
#define MIDI_B 2048
#define BOTI_B 2048
#define TRAN_B 2048
#define GRID_B (TOPZ_B + TOPM_B + MIDI_B + BOTI_B + TRAN_B)   // 7296

__device__ __forceinline__ uint32_t smem_u32(const void* p) {
    uint32_t a;
    asm("{ .reg .u64 t; cvta.to.shared.u64 t, %1; cvt.u32.u64 %0, t; }"
        : "=r"(a) : "l"(p));
    return a;
}

__device__ __forceinline__ void bulk_store(void* gptr, uint32_t saddr, uint32_t bytes) {
    asm volatile("cp.async.bulk.global.shared::cta.bulk_group [%0], [%1], %2;"
                 :: "l"(gptr), "r"(saddr), "r"(bytes) : "memory");
}

__device__ __forceinline__ void bulk_commit_wait() {
    asm volatile("cp.async.bulk.commit_group;" ::: "memory");
    asm volatile("cp.async.bulk.wait_group 0;" ::: "memory");
}

__global__ void __launch_bounds__(256)
coeff_build_kernel(const float* __restrict__ M,
                   const float* __restrict__ params,
                   const float* __restrict__ sw_params,
                   const int*   __restrict__ kinds,
                   const int*   __restrict__ time_ptr,
                   float*       __restrict__ out)
{
    // [0, 5120): row image / zero buffer (20 KB, TMA source)
    // [5120, 6176): transpose tile (32x33) — disjoint from the TMA region so a
    //               new transpose CTA can never corrupt an in-flight bulk read.
    __shared__ __align__(16) float sh[5120 + 1056];
    float4* img4 = reinterpret_cast<float4*>(sh);
    float (*tile)[33] = reinterpret_cast<float (*)[33]>(sh + 5120);

    const int b   = blockIdx.x;
    const int tid = threadIdx.x;
    const float4 zero4 = make_float4(0.f, 0.f, 0.f, 0.f);

    if (b < TOPZ_B) {
        // ---- TOPZ: zeros, TOP rows r0..r0+7, cols [2048, 5120) (12288 B) ----
        #pragma unroll
        for (int k = 0; k < 3; k++) img4[tid + k * 256] = zero4;
        __syncthreads();
        if (tid == 0) {
            asm volatile("fence.proxy.async;" ::: "memory");
            const uint32_t s = smem_u32(sh);
            const int r0 = b * 8;
            #pragma unroll
            for (int i = 0; i < 8; i++)
                bulk_store(out + (size_t)(r0 + i) * CC + EE, s, 12288u);
            bulk_commit_wait();
        }
        return;
    }

    if (b < TOPZ_B + TOPM_B) {
        // ---- TOPM: direct copy of M row into TOP row cols [0, 2048) ----
        const int row = b - TOPZ_B;
        const float4* Mrow = reinterpret_cast<const float4*>(M + (size_t)row * EE);
        float4* orow = reinterpret_cast<float4*>(out) + (size_t)row * C4;
        orow[tid]       = Mrow[tid];
        orow[tid + 256] = Mrow[tid + 256];
        return;
    }

    if (b < TOPZ_B + TOPM_B + MIDI_B) {
        // ---- MID: row N+e, cols [0, 4096). Image = zeros + 1.0 at col E+e ----
        const int e = b - (TOPZ_B + TOPM_B);
        #pragma unroll
        for (int k = 0; k < 4; k++) img4[tid + k * 256] = zero4;
        __syncthreads();
        if (tid == 0) {
            sh[EE + e] = 1.0f;
            asm volatile("fence.proxy.async;" ::: "memory");
            bulk_store(out + (size_t)(NN + e) * CC, smem_u32(sh), 16384u);
            bulk_commit_wait();
        }
        return;
    }

    if (b < TOPZ_B + TOPM_B + MIDI_B + BOTI_B) {
        // ---- BOT: full row N+E+e. Image = zeros + z at col e, y at col E+e ----
        const int e = b - (TOPZ_B + TOPM_B + MIDI_B);

        // tid 0 issues its operand loads first so latency overlaps the fill.
        float p = 0.f, sw = 0.f;
        int kk = 0, tm = 0;
        if (tid == 0) {
            tm = *time_ptr;
            p  = params[e];
            kk = kinds[e];
            sw = sw_params[(size_t)e * SIGW + tm];
        }

        #pragma unroll
        for (int k = 0; k < 5; k++) img4[tid + k * 256] = zero4;
        __syncthreads();

        if (tid == 0) {
            const bool  sw_on = sw > 0.0f;        // sigmoid(x)>0.5 <=> x>0
            const float ndt   = -DTC / p;
            float z, y;
            switch (kk) {
                case 0:  z = -p;                  y = 1.0f;                 break; // R
                case 1:  z = 0.0f;                y = 1.0f;                 break; // IVS
                case 2:  z = 1.0f;                y = 0.0f;                 break; // VC
                case 3:  z = sw_on ? 0.0f : 1.0f; y = sw_on ? 1.0f : 0.0f;  break; // SW
                case 4:  z = ndt;                 y = 1.0f;                 break; // C
                default: z = 1.0f;                y = ndt;                  break; // L
            }
            sh[e]      = z;
            sh[EE + e] = y;
            asm volatile("fence.proxy.async;" ::: "memory");
            bulk_store(out + (size_t)(NN + EE + e) * CC, smem_u32(sh), 20480u);
            bulk_commit_wait();
        }
        return;
    }

    // ---- TR: -M^T via smem transpose: out[N+e][2E+n] = -M[n][e] ----
    {
        const int t  = b - (TOPZ_B + TOPM_B + MIDI_B + BOTI_B);
        const int tn = t & 31;              // 32 tiles along n
        const int te = t >> 5;              // 64 tiles along e
        const int n0 = tn * 32;
        const int e0 = te * 32;
        const int tx = tid & 31;
        const int ty = tid >> 5;            // 0..7

        #pragma unroll
        for (int i = 0; i < 4; i++) {
            const int r = ty + i * 8;       // local n
            tile[r][tx] = M[(size_t)(n0 + r) * EE + (e0 + tx)];
        }
        __syncthreads();

        const int r = tid >> 3;             // local e, 0..31
        const int q = tid & 7;              // float4 slot along n
        float4 v;
        v.x = -tile[q * 4 + 0][r];
        v.y = -tile[q * 4 + 1][r];
        v.z = -tile[q * 4 + 2][r];
        v.w = -tile[q * 4 + 3][r];
        *reinterpret_cast<float4*>(
            out + (size_t)(NN + e0 + r) * CC + (2 * EE + n0 + q * 4)) = v;
    }
}

extern "C" void kernel_launch(void* const* d_in, const int* in_sizes, int n_in,
                              void* d_out, int out_size)
{
    const float* M         = (const float*)d_in[0];
    const float* params    = (const float*)d_in[1];
    const float* sw_params = (const float*)d_in[2];
    const int*   kinds     = (const int*)d_in[3];
    const int*   time_ptr  = (const int*)d_in[4];

    coeff_build_kernel<<<GRID_B, 256>>>(M, params, sw_params, kinds, time_ptr,
                                        (float*)d_out);
}

// round 8
// speedup vs baseline: 1.0903x; 1.0097x over previous
#include <cuda_runtime.h>

// Output: [N+2E, 2E+N] = [5120, 5120] float32, row-major.
//   rows [0, N):        [ M (N x E) | 0 | 0 ]
//   rows [N, N+E):      [ 0 | I_E | -M^T (E x N) ]
//   rows [N+E, N+2E):   [ diag(z) | diag(y) | 0 ]
//
// All-STG, deep-MLP variant. Block roles (heavy first):
//   [0, 512):      BOT : 4 rows/blk, full 1280 f4/row (20 STG/thread) + z/y diag
//   [512, 1024):   MID : 4 rows/blk, cols [0,4096) = 1024 f4/row (16 STG/thread) + I
//   [1024, 1280):  TOPZ: 4 rows/blk, cols [2048,5120) = 768 f4/row (12 STG/thread)
//   [1280, 1792):  TOPM: 2 rows/blk, M copy 512 f4/row (4 LDG + 4 STG/thread)
//   [1792, 3840):  TR  : -M^T 32x32 smem transpose

#define NN   1024
#define EE   2048
#define SIGW 64
#define CC   (2 * EE + NN)   // 5120
#define C4   (CC / 4)        // 1280
#define DTC  1e-6f

#define BOT_B  512
#define MID_B  512
#define TOPZ_B 256
#define TOPM_B 512
#define TR_B   2048
#define GRID_B (BOT_B + MID_B + TOPZ_B + TOPM_B + TR_B)   // 3840

__global__ void __launch_bounds__(256)
coeff_build_kernel(const float* __restrict__ M,
                   const float* __restrict__ params,
                   const float* __restrict__ sw_params,
                   const int*   __restrict__ kinds,
                   const int*   __restrict__ time_ptr,
                   float*       __restrict__ out)
{
    __shared__ float tile[32][33];

    const int b   = blockIdx.x;
    const int tid = threadIdx.x;
    const float4 zero4 = make_float4(0.f, 0.f, 0.f, 0.f);
    float4* out4 = reinterpret_cast<float4*>(out);

    if (b < BOT_B) {
        // ---- BOT: rows N+E+e, e = 4b..4b+3. diag(z) @ col e, diag(y) @ E+e.
        const int e0 = b * 4;
        const int tm = *time_ptr;
        #pragma unroll
        for (int r = 0; r < 4; r++) {
            const int e = e0 + r;
            // Block-uniform broadcast loads (cached).
            const float p     = __ldg(params + e);
            const int   kk    = __ldg(kinds + e);
            const bool  sw_on = __ldg(sw_params + (size_t)e * SIGW + tm) > 0.0f;
            const float ndt   = -DTC / p;
            float z, y;
            switch (kk) {
                case 0:  z = -p;                  y = 1.0f;                 break; // R
                case 1:  z = 0.0f;                y = 1.0f;                 break; // IVS
                case 2:  z = 1.0f;                y = 0.0f;                 break; // VC
                case 3:  z = sw_on ? 0.0f : 1.0f; y = sw_on ? 1.0f : 0.0f;  break; // SW
                case 4:  z = ndt;                 y = 1.0f;                 break; // C
                default: z = 1.0f;                y = ndt;                  break; // L
            }
            const int zf4  = e >> 2;
            const int yf4  = 512 + (e >> 2);
            const int comp = e & 3;
            float4* orow = out4 + (size_t)(NN + EE + e) * C4;
            #pragma unroll
            for (int k = 0; k < 5; k++) {
                const int c4 = tid + k * 256;
                float4 v = zero4;
                if (c4 == zf4) ((float*)&v)[comp] = z;
                if (c4 == yf4) ((float*)&v)[comp] = y;
                orow[c4] = v;
            }
        }
        return;
    }

    if (b < BOT_B + MID_B) {
        // ---- MID: rows N+e, e = 4t..4t+3, cols [0,4096): zeros + I @ col E+e.
        const int e0 = (b - BOT_B) * 4;
        #pragma unroll
        for (int r = 0; r < 4; r++) {
            const int e    = e0 + r;
            const int idf4 = 512 + (e >> 2);
            const int comp = e & 3;
            float4* orow = out4 + (size_t)(NN + e) * C4;
            #pragma unroll
            for (int k = 0; k < 4; k++) {
                const int c4 = tid + k * 256;
                float4 v = zero4;
                if (c4 == idf4) ((float*)&v)[comp] = 1.0f;
                orow[c4] = v;
            }
        }
        return;
    }

    if (b < BOT_B + MID_B + TOPZ_B) {
        // ---- TOPZ: rows 4t..4t+3, cols [2048,5120) = f4 [512,1280): zeros.
        const int r0 = (b - BOT_B - MID_B) * 4;
        #pragma unroll
        for (int r = 0; r < 4; r++) {
            float4* orow = out4 + (size_t)(r0 + r) * C4;
            #pragma unroll
            for (int k = 0; k < 3; k++)
                orow[512 + tid + k * 256] = zero4;
        }
        return;
    }

    if (b < BOT_B + MID_B + TOPZ_B + TOPM_B) {
        // ---- TOPM: rows 2t, 2t+1: copy M row into cols [0,2048).
        const int r0 = (b - BOT_B - MID_B - TOPZ_B) * 2;
        #pragma unroll
        for (int r = 0; r < 2; r++) {
            const float4* Mrow = reinterpret_cast<const float4*>(M + (size_t)(r0 + r) * EE);
            float4* orow = out4 + (size_t)(r0 + r) * C4;
            orow[tid]       = Mrow[tid];
            orow[tid + 256] = Mrow[tid + 256];
        }
        return;
    }

    // ---- TR: -M^T via smem transpose: out[N+e][2E+n] = -M[n][e].
    {
        const int t  = b - (BOT_B + MID_B + TOPZ_B + TOPM_B);
        const int tn = t & 31;              // 32 tiles along n
        const int te = t >> 5;              // 64 tiles along e
        const int n0 = tn * 32;
        const int e0 = te * 32;
        const int tx = tid & 31;
        const int ty = tid >> 5;            // 0..7

        #pragma unroll
        for (int i = 0; i < 4; i++) {
            const int r = ty + i * 8;       // local n
            tile[r][tx] = M[(size_t)(n0 + r) * EE + (e0 + tx)];
        }
        __syncthreads();

        const int r = tid >> 3;             // local e, 0..31
        const int q = tid & 7;              // float4 slot along n
        float4 v;
        v.x = -tile[q * 4 + 0][r];
        v.y = -tile[q * 4 + 1][r];
        v.z = -tile[q * 4 + 2][r];
        v.w = -tile[q * 4 + 3][r];
        *reinterpret_cast<float4*>(
            out + (size_t)(NN + e0 + r) * CC + (2 * EE + n0 + q * 4)) = v;
    }
}

extern "C" void kernel_launch(void* const* d_in, const int* in_sizes, int n_in,
                              void* d_out, int out_size)
{
    const float* M         = (const float*)d_in[0];
    const float* params    = (const float*)d_in[1];
    const float* sw_params = (const float*)d_in[2];
    const int*   kinds     = (const int*)d_in[3];
    const int*   time_ptr  = (const int*)d_in[4];

    coeff_build_kernel<<<GRID_B, 256>>>(M, params, sw_params, kinds, time_ptr,
                                        (float*)d_out);
}

// round 9
// speedup vs baseline: 1.1840x; 1.0860x over previous
#include <cuda_runtime.h>

// Output: [N+2E, 2E+N] = [5120, 5120] float32, row-major.
//   rows [0, N):        [ M (N x E) | 0 | 0 ]
//   rows [N, N+E):      [ 0 | I_E | -M^T (E x N) ]
//   rows [N+E, N+2E):   [ diag(z) | diag(y) | 0 ]
//
// All regions except the transpose use 256-bit stores (st.global.v8.f32).
// Every data block handles 2 rows; warps 0-3 take row0, warps 4-7 take row1.
// Block roles:
//   [0, 1024):     BOT: rows N+E+{2b,2b+1}, full row (640 f8) + z/y diag
//   [1024, 2048):  MID: rows N+{2b,2b+1}, cols [0,4096) (512 f8) + identity
//   [2048, 2560):  TOP: rows {2b,2b+1}: M copy (256 f8) + zeros (384 f8)
//   [2560, 4608):  TR : -M^T 32x32 smem transpose (float4 stores)

#define NN   1024
#define EE   2048
#define SIGW 64
#define CC   (2 * EE + NN)   // 5120
#define C8   (CC / 8)        // 640 v8-chunks per full row
#define DTC  1e-6f

#define BOT_B 1024
#define MID_B 1024
#define TOP_B 512
#define TR_B  2048
#define GRID_B (BOT_B + MID_B + TOP_B + TR_B)   // 4608

__device__ __forceinline__ void stg256(float* p, const float* v) {
    asm volatile("st.global.v8.f32 [%0], {%1,%2,%3,%4,%5,%6,%7,%8};"
                 :: "l"(p), "f"(v[0]), "f"(v[1]), "f"(v[2]), "f"(v[3]),
                    "f"(v[4]), "f"(v[5]), "f"(v[6]), "f"(v[7])
                 : "memory");
}

__device__ __forceinline__ void ldg_stg256(float* dst, const float* src) {
    float a, b, c, d, e, f, g, h;
    asm volatile("ld.global.nc.v8.f32 {%0,%1,%2,%3,%4,%5,%6,%7}, [%8];"
                 : "=f"(a), "=f"(b), "=f"(c), "=f"(d),
                   "=f"(e), "=f"(f), "=f"(g), "=f"(h)
                 : "l"(src));
    asm volatile("st.global.v8.f32 [%0], {%1,%2,%3,%4,%5,%6,%7,%8};"
                 :: "l"(dst), "f"(a), "f"(b), "f"(c), "f"(d),
                    "f"(e), "f"(f), "f"(g), "f"(h)
                 : "memory");
}

__global__ void __launch_bounds__(256)
coeff_build_kernel(const float* __restrict__ M,
                   const float* __restrict__ params,
                   const float* __restrict__ sw_params,
                   const int*   __restrict__ kinds,
                   const int*   __restrict__ time_ptr,
                   float*       __restrict__ out)
{
    __shared__ float tile[32][33];

    const int b    = blockIdx.x;
    const int tid  = threadIdx.x;
    const int half = tid >> 7;      // 0 or 1: which of the block's 2 rows
    const int ht   = tid & 127;     // lane within the half-block

    const float zero8[8] = {0.f, 0.f, 0.f, 0.f, 0.f, 0.f, 0.f, 0.f};

    if (b < BOT_B) {
        // ---- BOT: row N+E+e, full row. z @ col e, y @ col E+e. ----
        const int e = b * 2 + half;
        const int   tm    = *time_ptr;
        const float p     = __ldg(params + e);
        const int   kk    = __ldg(kinds + e);
        const bool  sw_on = __ldg(sw_params + (size_t)e * SIGW + tm) > 0.0f; // sigmoid>0.5 <=> x>0
        const float ndt   = -DTC / p;
        float z, y;
        switch (kk) {
            case 0:  z = -p;                  y = 1.0f;                 break; // R
            case 1:  z = 0.0f;                y = 1.0f;                 break; // IVS
            case 2:  z = 1.0f;                y = 0.0f;                 break; // VC
            case 3:  z = sw_on ? 0.0f : 1.0f; y = sw_on ? 1.0f : 0.0f;  break; // SW
            case 4:  z = ndt;                 y = 1.0f;                 break; // C
            default: z = 1.0f;                y = ndt;                  break; // L
        }
        const int zf8  = e >> 3;
        const int yf8  = 256 + (e >> 3);
        const int comp = e & 7;
        float* row = out + (size_t)(NN + EE + e) * CC;
        #pragma unroll
        for (int j = 0; j < 5; j++) {
            const int c8 = ht + j * 128;
            float v[8] = {0.f, 0.f, 0.f, 0.f, 0.f, 0.f, 0.f, 0.f};
            if (c8 == zf8) v[comp] = z;
            if (c8 == yf8) v[comp] = y;
            stg256(row + c8 * 8, v);
        }
        return;
    }

    if (b < BOT_B + MID_B) {
        // ---- MID: row N+e, cols [0,4096) = 512 f8. Identity @ col E+e. ----
        const int e = (b - BOT_B) * 2 + half;
        const int idf8 = 256 + (e >> 3);
        const int comp = e & 7;
        float* row = out + (size_t)(NN + e) * CC;
        #pragma unroll
        for (int j = 0; j < 4; j++) {
            const int c8 = ht + j * 128;
            float v[8] = {0.f, 0.f, 0.f, 0.f, 0.f, 0.f, 0.f, 0.f};
            if (c8 == idf8) v[comp] = 1.0f;
            stg256(row + c8 * 8, v);
        }
        return;
    }

    if (b < BOT_B + MID_B + TOP_B) {
        // ---- TOP: row r: copy M (256 f8) + zeros (384 f8). ----
        const int r = (b - BOT_B - MID_B) * 2 + half;
        const float* Mrow = M + (size_t)r * EE;
        float* row = out + (size_t)r * CC;
        // Copy cols [0, 2048): f8 indices ht, ht+128.
        ldg_stg256(row + (size_t)ht * 8,         Mrow + (size_t)ht * 8);
        ldg_stg256(row + (size_t)(ht + 128) * 8, Mrow + (size_t)(ht + 128) * 8);
        // Zeros cols [2048, 5120): f8 indices 256 + ht + j*128, j=0..2.
        #pragma unroll
        for (int j = 0; j < 3; j++)
            stg256(row + (size_t)(256 + ht + j * 128) * 8, zero8);
        return;
    }

    // ---- TR: -M^T via smem transpose: out[N+e][2E+n] = -M[n][e]. ----
    {
        const int t  = b - (BOT_B + MID_B + TOP_B);
        const int tn = t & 31;              // 32 tiles along n
        const int te = t >> 5;              // 64 tiles along e
        const int n0 = tn * 32;
        const int e0 = te * 32;
        const int tx = tid & 31;
        const int ty = tid >> 5;            // 0..7

        #pragma unroll
        for (int i = 0; i < 4; i++) {
            const int r = ty + i * 8;       // local n
            tile[r][tx] = M[(size_t)(n0 + r) * EE + (e0 + tx)];
        }
        __syncthreads();

        const int r = tid >> 3;             // local e, 0..31
        const int q = tid & 7;              // float4 slot along n
        float4 v;
        v.x = -tile[q * 4 + 0][r];
        v.y = -tile[q * 4 + 1][r];
        v.z = -tile[q * 4 + 2][r];
        v.w = -tile[q * 4 + 3][r];
        *reinterpret_cast<float4*>(
            out + (size_t)(NN + e0 + r) * CC + (2 * EE + n0 + q * 4)) = v;
    }
}

extern "C" void kernel_launch(void* const* d_in, const int* in_sizes, int n_in,
                              void* d_out, int out_size)
{
    const float* M         = (const float*)d_in[0];
    const float* params    = (const float*)d_in[1];
    const float* sw_params = (const float*)d_in[2];
    const int*   kinds     = (const int*)d_in[3];
    const int*   time_ptr  = (const int*)d_in[4];

    coeff_build_kernel<<<GRID_B, 256>>>(M, params, sw_params, kinds, time_ptr,
                                        (float*)d_out);
}